// round 11
// baseline (speedup 1.0000x reference)
#include <cuda_runtime.h>
#include <cuda_bf16.h>
#include <math.h>
#include <stdint.h>

#define NPTS 32768
#define TILE 64
#define NTHR 1024
#define NCTA 148
#define CPE  81
#define NCHUNKS (8 * CPE)

__device__ int g_cnt[8];
__device__ int g_list[8 * NPTS];
__device__ __align__(16) __nv_bfloat16 Whi_g[(size_t)NCHUNKS * 10240];
__device__ __align__(16) __nv_bfloat16 Wlo_g[(size_t)NCHUNKS * 10240];

// ---- smem layout (bytes) ----
#define SB_WS    0                /* 2 x 40960 (hi 20480 + lo 20480) */
#define SB_AH    81920            /* 64 x 784 = 50176 */
#define SB_AL    132096           /* 50176 */
#define SB_GIDX  182272           /* 256 */
#define SB_WD    182528           /* 1024 */
#define SB_WC2   183552           /* 1552 */
#define SB_DENSP 185104           /* 2048 */
#define SB_COLP  187152           /* 3072 */
#define SMEM_BYTES 190224

// ---------------- helpers ----------------
__device__ __forceinline__ uint32_t smem_u32(const void* p) {
    uint32_t a;
    asm("{ .reg .u64 t; cvta.to.shared.u64 t, %1; cvt.u32.u64 %0, t; }" : "=r"(a) : "l"(p));
    return a;
}
__device__ __forceinline__ void cpasync16(uint32_t sa, const void* g) {
    asm volatile("cp.async.cg.shared.global [%0], [%1], 16;" :: "r"(sa), "l"(g));
}
__device__ __forceinline__ void cp_commit() { asm volatile("cp.async.commit_group;"); }
__device__ __forceinline__ void cp_wait0()  { asm volatile("cp.async.wait_group 0;"); }

__device__ __forceinline__ void mma16816(float* d, const uint32_t* a, uint32_t b0, uint32_t b1) {
    asm volatile("mma.sync.aligned.m16n8k16.row.col.f32.bf16.bf16.f32 "
                 "{%0,%1,%2,%3}, {%4,%5,%6,%7}, {%8,%9}, {%0,%1,%2,%3};"
                 : "+f"(d[0]), "+f"(d[1]), "+f"(d[2]), "+f"(d[3])
                 : "r"(a[0]), "r"(a[1]), "r"(a[2]), "r"(a[3]), "r"(b0), "r"(b1));
}
__device__ __forceinline__ void ldsm4(uint32_t* r, uint32_t addr) {
    asm volatile("ldmatrix.sync.aligned.m8n8.x4.shared.b16 {%0,%1,%2,%3}, [%4];"
                 : "=r"(r[0]), "=r"(r[1]), "=r"(r[2]), "=r"(r[3]) : "r"(addr));
}

// fast accurate sincos: fp64 range reduction + fp32 poly (~1e-7 abs)
__device__ __forceinline__ void sincos_acc(float a, float* so, float* co) {
    double ad = (double)a;
    double kd = rint(ad * 0.6366197723675814);            // 2/pi
    double r  = fma(-kd, 1.5707963267948966, ad);
    r = fma(-kd, 6.123233995736766e-17, r);
    float rf = (float)r;
    float r2 = rf * rf;
    float sp = fmaf(r2, fmaf(r2, fmaf(r2, fmaf(r2, 2.7557314e-6f, -1.9841249e-4f),
                    8.3333338e-3f), -1.6666667e-1f), 1.0f);
    sp *= rf;
    float cp = fmaf(r2, fmaf(r2, fmaf(r2, fmaf(r2, -2.7557319e-7f, 2.4801587e-5f),
                    -1.3888889e-3f), 4.1666668e-2f), 0.0f);
    cp = fmaf(r2, cp, fmaf(r2, -0.5f, 1.0f));
    int q = ((int)kd) & 3;
    float s, c;
    if (q == 0)      { s =  sp; c =  cp; }
    else if (q == 1) { s =  cp; c = -sp; }
    else if (q == 2) { s = -sp; c = -cp; }
    else             { s = -cp; c =  sp; }
    *so = s; *co = c;
}

// ---------------- routing ----------------
__global__ void k_zero() { if (threadIdx.x < 8) g_cnt[threadIdx.x] = 0; }

__global__ void k_route(const float* __restrict__ pts, float* __restrict__ out) {
    int i = blockIdx.x * blockDim.x + threadIdx.x;
    if (i >= NPTS) return;
    float x = pts[3 * i], y = pts[3 * i + 1], z = pts[3 * i + 2];
    bool fg = (x >= -80.f) && (x <= 80.f) && (y >= -80.f) && (y <= 80.f)
           && (z >= -4.f) && (z <= 44.f);
    if (!fg) {
        out[i] = 0.f;
        out[NPTS + 3 * i] = 0.f; out[NPTS + 3 * i + 1] = 0.f; out[NPTS + 3 * i + 2] = 0.f;
        return;
    }
    int jx = (x > 0.f) ? 1 : 0;
    int iy = (y > 50.f) ? 3 : (y > 0.f) ? 2 : (y > -50.f) ? 1 : 0;
    int e = iy * 2 + jx;
    int pos = atomicAdd(&g_cnt[e], 1);
    g_list[e * NPTS + pos] = i;
}

// ==== weight prep: f32 [K][N] -> bf16 hi/lo transposed [256 n][32 k] chunks ====
__global__ void k_prep(const float* __restrict__ W0, const float* __restrict__ Wpre,
                       const float* __restrict__ Wskip, const float* __restrict__ Wpost,
                       const float* __restrict__ Wf, const float* __restrict__ Wc1) {
    int ch = blockIdx.x;
    int e = ch / CPE, r = ch % CPE;
    const float* src; int K, N, k0;
    if (r < 4)       { src = W0    + (size_t)e * 111 * 256; K = 111; N = 256; k0 = r * 32; }
    else if (r < 28) { int i = (r - 4) >> 3;  src = Wpre  + ((size_t)e * 3 + i) * 65536; K = 256; N = 256; k0 = ((r - 4) & 7) * 32; }
    else if (r < 40) { src = Wskip + (size_t)e * 367 * 256; K = 367; N = 256; k0 = (r - 28) * 32; }
    else if (r < 64) { int i = (r - 40) >> 3; src = Wpost + ((size_t)e * 3 + i) * 65536; K = 256; N = 256; k0 = ((r - 40) & 7) * 32; }
    else if (r < 72) { src = Wf    + (size_t)e * 65536;     K = 256; N = 256; k0 = (r - 64) * 32; }
    else             { src = Wc1   + (size_t)e * 283 * 128; K = 283; N = 128; k0 = (r - 72) * 32; }
    int n = threadIdx.x;   // 0..255
    __nv_bfloat16 hi[32], lo[32];
#pragma unroll 8
    for (int kk = 0; kk < 32; kk++) {
        int k = k0 + kk;
        float v = (k < K && n < N) ? src[(size_t)k * N + n] : 0.f;
        __nv_bfloat16 h = __float2bfloat16(v);
        hi[kk] = h;
        lo[kk] = __float2bfloat16(v - __bfloat162float(h));
    }
    char* dh = (char*)Whi_g + (size_t)ch * 20480 + n * 80;
    char* dl = (char*)Wlo_g + (size_t)ch * 20480 + n * 80;
#pragma unroll
    for (int g = 0; g < 4; g++) {
        *(uint4*)(dh + g * 16) = *(uint4*)&hi[g * 8];
        *(uint4*)(dl + g * 16) = *(uint4*)&lo[g * 8];
    }
}

// ---------------- W chunk staging ----------------
__device__ __forceinline__ void stageW(char* smp, int buf, int chunk, int tid) {
    const char* sh = (const char*)Whi_g + (size_t)chunk * 20480;
    const char* sl = (const char*)Wlo_g + (size_t)chunk * 20480;
    uint32_t sa = smem_u32(smp + SB_WS + buf * 40960);
    for (int u = tid; u < 1280; u += NTHR) {
        cpasync16(sa + u * 16, sh + u * 16);
        cpasync16(sa + 20480 + u * 16, sl + u * 16);
    }
}

// ---------------- one GEMM layer over a 64-pt tile, 32 warps ----------------
// Warp w: m = w&3 (16 rows), ng = w>>2 (32 cols).
// mode: 0 relu+writeA ; 1 relu+writeA+density ; 2 writeA no relu ; 3 relu+color (N=128)
__device__ __noinline__ void gemm_layer(char* smp, int cbase, int nch, int acolb,
                                        int mode, const float* __restrict__ bias) {
    const int tid = threadIdx.x;
    const int w = tid >> 5, l = tid & 31;
    const int m = w & 3, ng = w >> 2;
    const int gid = l >> 2, tig = l & 3;
    const bool active = (mode == 3) ? (ng < 4) : true;

    float acc[4][4];
#pragma unroll
    for (int nt = 0; nt < 4; nt++)
#pragma unroll
        for (int j = 0; j < 4; j++) acc[nt][j] = 0.f;

    stageW(smp, 0, cbase, tid);
    cp_commit();

    // ldmatrix lane addresses (x4):
    // A: matrices {rows0-7 k0-7, rows8-15 k0-7, rows0-7 k8-15, rows8-15 k8-15}
    const uint32_t ah_base = smem_u32(smp + SB_AH)
        + (uint32_t)((m * 16 + (l & 7) + ((l >> 3) & 1) * 8) * 784 + acolb + (l >> 4) * 16);
    const uint32_t al_base = ah_base + (uint32_t)(SB_AL - SB_AH);
    // B: matrices {n0-7 k0-7, n0-7 k8-15, n8-15 k0-7, n8-15 k8-15}
    const uint32_t ws_base = smem_u32(smp + SB_WS);
    const uint32_t brow_off = (uint32_t)(((l & 7) + ((l >> 4) & 1) * 8) * 80 + ((l >> 3) & 1) * 16);
    const uint32_t b_p0 = (uint32_t)(ng * 32 * 80) + brow_off;

    for (int c = 0; c < nch; c++) {
        cp_wait0();
        __syncthreads();
        if (c + 1 < nch) { stageW(smp, (c + 1) & 1, cbase + c + 1, tid); cp_commit(); }
        if (active) {
            uint32_t wb = ws_base + (uint32_t)((c & 1) * 40960);
#pragma unroll
            for (int ks2 = 0; ks2 < 2; ks2++) {
                uint32_t ka = (uint32_t)(c * 64 + ks2 * 32);
                uint32_t ah[4], al[4];
                ldsm4(ah, ah_base + ka);
                ldsm4(al, al_base + ka);
#pragma unroll
                for (int p = 0; p < 2; p++) {
                    uint32_t bh[4], bl[4];
                    uint32_t bo = wb + b_p0 + (uint32_t)(p * 16 * 80 + ks2 * 32);
                    ldsm4(bh, bo);
                    ldsm4(bl, bo + 20480u);
#pragma unroll
                    for (int q = 0; q < 2; q++) {
                        int nt = p * 2 + q;
                        mma16816(acc[nt], ah, bh[2 * q], bh[2 * q + 1]);
                        mma16816(acc[nt], al, bh[2 * q], bh[2 * q + 1]);
                        mma16816(acc[nt], ah, bl[2 * q], bl[2 * q + 1]);
                    }
                }
            }
        }
    }

    __syncthreads();   // all A reads done before in-place writeback
    if (active) {
        float dp[2];
        float cp3[2][3];
        dp[0] = dp[1] = 0.f;
#pragma unroll
        for (int hf = 0; hf < 2; hf++) { cp3[hf][0] = 0.f; cp3[hf][1] = 0.f; cp3[hf][2] = 0.f; }
        float* WdS  = (float*)(smp + SB_WD);
        float* Wc2S = (float*)(smp + SB_WC2);
#pragma unroll
        for (int nt = 0; nt < 4; nt++) {
            int c0 = ng * 32 + nt * 8 + 2 * tig;
            float b0v = __ldg(bias + c0), b1v = __ldg(bias + c0 + 1);
            float v0 = acc[nt][0] + b0v;
            float v1 = acc[nt][1] + b1v;
            float v2 = acc[nt][2] + b0v;
            float v3 = acc[nt][3] + b1v;
            if (mode != 2) {
                v0 = fmaxf(v0, 0.f); v1 = fmaxf(v1, 0.f);
                v2 = fmaxf(v2, 0.f); v3 = fmaxf(v3, 0.f);
            }
            if (mode == 1) {
                dp[0] += v0 * WdS[c0] + v1 * WdS[c0 + 1];
                dp[1] += v2 * WdS[c0] + v3 * WdS[c0 + 1];
            }
            if (mode == 3) {
#pragma unroll
                for (int chn = 0; chn < 3; chn++) {
                    cp3[0][chn] += v0 * Wc2S[c0 * 3 + chn] + v1 * Wc2S[(c0 + 1) * 3 + chn];
                    cp3[1][chn] += v2 * Wc2S[c0 * 3 + chn] + v3 * Wc2S[(c0 + 1) * 3 + chn];
                }
            } else {
                uint32_t off0 = (uint32_t)((m * 16 + gid) * 784 + c0 * 2);
                uint32_t off1 = off0 + 8u * 784u;
                __nv_bfloat16 h0 = __float2bfloat16(v0), h1 = __float2bfloat16(v1);
                __nv_bfloat16 h2 = __float2bfloat16(v2), h3 = __float2bfloat16(v3);
                __nv_bfloat162 H0 = __halves2bfloat162(h0, h1);
                __nv_bfloat162 H1 = __halves2bfloat162(h2, h3);
                __nv_bfloat162 L0 = __halves2bfloat162(
                    __float2bfloat16(v0 - __bfloat162float(h0)),
                    __float2bfloat16(v1 - __bfloat162float(h1)));
                __nv_bfloat162 L1 = __halves2bfloat162(
                    __float2bfloat16(v2 - __bfloat162float(h2)),
                    __float2bfloat16(v3 - __bfloat162float(h3)));
                *(uint32_t*)(smp + SB_AH + off0) = *(uint32_t*)&H0;
                *(uint32_t*)(smp + SB_AH + off1) = *(uint32_t*)&H1;
                *(uint32_t*)(smp + SB_AL + off0) = *(uint32_t*)&L0;
                *(uint32_t*)(smp + SB_AL + off1) = *(uint32_t*)&L1;
            }
        }
        if (mode == 1) {
#pragma unroll
            for (int hf = 0; hf < 2; hf++) {
                float s = dp[hf];
                s += __shfl_xor_sync(0xffffffffu, s, 1);
                s += __shfl_xor_sync(0xffffffffu, s, 2);
                if (tig == 0)
                    ((float*)(smp + SB_DENSP))[ng * 64 + m * 16 + hf * 8 + gid] = s;
            }
        }
        if (mode == 3) {
#pragma unroll
            for (int hf = 0; hf < 2; hf++)
#pragma unroll
                for (int chn = 0; chn < 3; chn++) {
                    float s = cp3[hf][chn];
                    s += __shfl_xor_sync(0xffffffffu, s, 1);
                    s += __shfl_xor_sync(0xffffffffu, s, 2);
                    if (tig == 0)
                        ((float*)(smp + SB_COLP))[(ng * 64 + m * 16 + hf * 8 + gid) * 3 + chn] = s;
                }
        }
    }
    __syncthreads();
}

// smem A-tile store (bf16 hi + lo)
__device__ __forceinline__ void a_store(char* smp, int p, int col, float v) {
    uint32_t off = (uint32_t)(p * 784 + col * 2);
    __nv_bfloat16 h = __float2bfloat16(v);
    *(__nv_bfloat16*)(smp + SB_AH + off) = h;
    *(__nv_bfloat16*)(smp + SB_AL + off) = __float2bfloat16(v - __bfloat162float(h));
}

// ---------------- main MLP kernel ----------------
__global__ void __launch_bounds__(NTHR, 1) k_mlp(
    const float* __restrict__ pts, const float* __restrict__ vds,
    const int* __restrict__ aidx, const float* __restrict__ app,
    const float* __restrict__ b0, const float* __restrict__ bpre,
    const float* __restrict__ bskip, const float* __restrict__ bpost,
    const float* __restrict__ Wd, const float* __restrict__ bd,
    const float* __restrict__ bf, const float* __restrict__ bc1,
    const float* __restrict__ Wc2, const float* __restrict__ bc2,
    float* __restrict__ out) {
    extern __shared__ char smp[];
    const int tid = threadIdx.x;

    int cnt8[8], tb[8], tot = 0;
#pragma unroll
    for (int e8 = 0; e8 < 8; e8++) {
        cnt8[e8] = g_cnt[e8]; tb[e8] = tot;
        tot += (cnt8[e8] + TILE - 1) / TILE;
    }
    int* gidx = (int*)(smp + SB_GIDX);
    float* WdS  = (float*)(smp + SB_WD);
    float* Wc2S = (float*)(smp + SB_WC2);

    for (int tile = blockIdx.x; tile < tot; tile += gridDim.x) {
        int e = 0;
#pragma unroll
        for (int e8 = 1; e8 < 8; e8++) if (tile >= tb[e8]) e = e8;
        const int base = (tile - tb[e]) * TILE;
        const int npts = min(TILE, cnt8[e] - base);
        const int eb = e * CPE;

        // zero A hi+lo (100352 B = 6272 uint4)
        for (int u = tid; u < 6272; u += NTHR)
            ((uint4*)(smp + SB_AH))[u] = make_uint4(0, 0, 0, 0);
        if (tid < 256) WdS[tid] = Wd[e * 256 + tid];
        if (tid >= 256 && tid < 643) {
            int j = tid - 256;
            Wc2S[j] = (j < 384) ? Wc2[e * 384 + j] : bc2[e * 3 + (j - 384)];
        }
        __syncthreads();

        // posenc + appearance -> A cols 256..366 (16 threads per point)
        {
            int pt = tid >> 4, q = tid & 15;
            if (pt < npts) {
                int g = g_list[e * NPTS + base + pt];
                float px = pts[3 * g], py = pts[3 * g + 1], pz = pts[3 * g + 2];
                if (q == 0) {
                    gidx[pt] = g;
                    a_store(smp, pt, 256, px); a_store(smp, pt, 257, py); a_store(smp, pt, 258, pz);
                }
                if (q < 10) {
                    float f = (float)exp2((double)q * (10.0 / 9.0));
                    int r = 256 + 3 + 6 * q;
                    float s, c;
                    sincos_acc(f * px, &s, &c); a_store(smp, pt, r + 0, s); a_store(smp, pt, r + 3, c);
                    sincos_acc(f * py, &s, &c); a_store(smp, pt, r + 1, s); a_store(smp, pt, r + 4, c);
                    sincos_acc(f * pz, &s, &c); a_store(smp, pt, r + 2, s); a_store(smp, pt, r + 5, c);
                }
                int ai = aidx[g];
                const float* a = app + ((size_t)e * 1000 + ai) * 48;
                for (int j = q; j < 48; j += 16) a_store(smp, pt, 256 + 63 + j, a[j]);
            } else if (q == 0) gidx[pt] = 0;
        }
        __syncthreads();

        // trunk
        gemm_layer(smp, eb + 0, 4, 512, 0, b0 + e * 256);                 // W0 (A cols 256+)
        for (int i = 0; i < 3; i++)
            gemm_layer(smp, eb + 4 + 8 * i, 8, 0, 0, bpre + (e * 3 + i) * 256);
        gemm_layer(smp, eb + 28, 12, 0, 0, bskip + e * 256);              // skip (K=384)

        // dir-enc overwrites x0 region cols 256..287 (also zero stale 283..287)
        {
            int pt = tid >> 4, q = tid & 15;
            if (pt < npts) {
                int g = gidx[pt];
                float vx = vds[3 * g], vy = vds[3 * g + 1], vz = vds[3 * g + 2];
                if (q < 4) {
                    float f = (float)exp2((double)q * (4.0 / 3.0));
                    int r = 256 + 3 + 6 * q;
                    float s, c;
                    sincos_acc(f * vx, &s, &c); a_store(smp, pt, r + 0, s); a_store(smp, pt, r + 3, c);
                    sincos_acc(f * vy, &s, &c); a_store(smp, pt, r + 1, s); a_store(smp, pt, r + 4, c);
                    sincos_acc(f * vz, &s, &c); a_store(smp, pt, r + 2, s); a_store(smp, pt, r + 5, c);
                } else if (q == 4) {
                    a_store(smp, pt, 256, vx); a_store(smp, pt, 257, vy); a_store(smp, pt, 258, vz);
                } else if (q == 5) {
                    for (int j = 283; j < 288; j++) a_store(smp, pt, j, 0.f);
                }
            }
        }
        __syncthreads();

        for (int i = 0; i < 3; i++)
            gemm_layer(smp, eb + 40 + 8 * i, 8, 0, (i == 2) ? 1 : 0, bpost + (e * 3 + i) * 256);

        // density finalize
        if (tid < 64) {
            float* dps = (float*)(smp + SB_DENSP);
            float s = bd[e];
#pragma unroll
            for (int ngx = 0; ngx < 8; ngx++) s += dps[ngx * 64 + tid];
            if (tid < npts) out[gidx[tid]] = fmaxf(s, 0.f);
        }

        gemm_layer(smp, eb + 64, 8, 0, 2, bf + e * 256);                   // feature
        gemm_layer(smp, eb + 72, 9, 0, 3, bc1 + e * 128);                  // color hidden

        // color finalize
        if (tid < 192) {
            int pt = tid / 3, chn = tid - 3 * pt;
            float* cps = (float*)(smp + SB_COLP);
            float s = Wc2S[384 + chn];
#pragma unroll
            for (int ngx = 0; ngx < 4; ngx++) s += cps[(ngx * 64 + pt) * 3 + chn];
            if (pt < npts) out[NPTS + 3 * gidx[pt] + chn] = 1.f / (1.f + expf(-s));
        }
        __syncthreads();   // smem reused next tile
    }
}

// ---------------- launch ----------------
extern "C" void kernel_launch(void* const* d_in, const int* in_sizes, int n_in,
                              void* d_out, int out_size) {
    const float* pts   = (const float*)d_in[0];
    const float* vds   = (const float*)d_in[1];
    const int*   aidx  = (const int*)d_in[2];
    const float* app   = (const float*)d_in[3];
    const float* W0    = (const float*)d_in[4];
    const float* b0    = (const float*)d_in[5];
    const float* Wpre  = (const float*)d_in[6];
    const float* bpre  = (const float*)d_in[7];
    const float* Wskip = (const float*)d_in[8];
    const float* bskip = (const float*)d_in[9];
    const float* Wpost = (const float*)d_in[10];
    const float* bpost = (const float*)d_in[11];
    const float* Wd    = (const float*)d_in[12];
    const float* bd    = (const float*)d_in[13];
    const float* Wf    = (const float*)d_in[14];
    const float* bf    = (const float*)d_in[15];
    const float* Wc1   = (const float*)d_in[16];
    const float* bc1   = (const float*)d_in[17];
    const float* Wc2   = (const float*)d_in[18];
    const float* bc2   = (const float*)d_in[19];
    float* out = (float*)d_out;

    static bool attr_done = false;
    if (!attr_done) {
        cudaFuncSetAttribute(k_mlp, cudaFuncAttributeMaxDynamicSharedMemorySize, SMEM_BYTES);
        attr_done = true;
    }

    k_prep<<<NCHUNKS, 256>>>(W0, Wpre, Wskip, Wpost, Wf, Wc1);
    k_zero<<<1, 32>>>();
    k_route<<<NPTS / 256, 256>>>(pts, out);
    k_mlp<<<NCTA, NTHR, SMEM_BYTES>>>(pts, vds, aidx, app, b0, bpre, bskip, bpost,
                                      Wd, bd, bf, bc1, Wc2, bc2, out);
}

// round 12
// speedup vs baseline: 1.0753x; 1.0753x over previous
#include <cuda_runtime.h>
#include <cuda_bf16.h>
#include <math.h>
#include <stdint.h>

#define NPTS 32768
#define TILE 64
#define NTHR 1024
#define NCTA 148
#define CPE  81
#define NCHUNKS (8 * CPE)

__device__ int g_cnt[8];
__device__ int g_list[8 * NPTS];
__device__ __align__(16) __nv_bfloat16 Whi_g[(size_t)NCHUNKS * 10240];
__device__ __align__(16) __nv_bfloat16 Wlo_g[(size_t)NCHUNKS * 10240];

// ---- smem layout (bytes) ----
#define SB_WS    0                /* 2 x 40960 (hi 20480 + lo 20480) */
#define SB_AH    81920            /* 64 x 784 = 50176 */
#define SB_AL    132096           /* 50176 */
#define SB_GIDX  182272           /* 256 */
#define SB_WD    182528           /* 1024 */
#define SB_WC2   183552           /* 1552 */
#define SB_DENSP 185104           /* 2048 */
#define SB_COLP  187152           /* 3072 */
#define SB_MBAR  190224           /* 2 x 8B mbarriers */
#define SMEM_BYTES 190240

// ---------------- helpers ----------------
__device__ __forceinline__ uint32_t smem_u32(const void* p) {
    uint32_t a;
    asm("{ .reg .u64 t; cvta.to.shared.u64 t, %1; cvt.u32.u64 %0, t; }" : "=r"(a) : "l"(p));
    return a;
}
__device__ __forceinline__ void mbar_init(uint32_t mb, uint32_t n) {
    asm volatile("mbarrier.init.shared.b64 [%0], %1;" :: "r"(mb), "r"(n) : "memory");
}
__device__ __forceinline__ void mbar_expect(uint32_t mb, uint32_t bytes) {
    asm volatile("mbarrier.arrive.expect_tx.shared.b64 _, [%0], %1;" :: "r"(mb), "r"(bytes) : "memory");
}
__device__ __forceinline__ void waitp(uint32_t mb, uint32_t par) {
    uint32_t done;
    asm volatile("{ .reg .pred p; mbarrier.try_wait.parity.acquire.cta.shared::cta.b64 p, [%1], %2; selp.b32 %0, 1, 0, p; }"
                 : "=r"(done) : "r"(mb), "r"(par) : "memory");
    while (!done) {
        asm volatile("{ .reg .pred p; mbarrier.try_wait.parity.acquire.cta.shared::cta.b64 p, [%1], %2, 0x989680; selp.b32 %0, 1, 0, p; }"
                     : "=r"(done) : "r"(mb), "r"(par) : "memory");
    }
}
__device__ __forceinline__ void bulkcp(uint32_t dst, const void* src, uint32_t bytes, uint32_t mb) {
    asm volatile("cp.async.bulk.shared::cluster.global.mbarrier::complete_tx::bytes [%0], [%1], %2, [%3];"
                 :: "r"(dst), "l"(src), "r"(bytes), "r"(mb) : "memory");
}
__device__ __forceinline__ void mma16816(float* d, const uint32_t* a, uint32_t b0, uint32_t b1) {
    asm volatile("mma.sync.aligned.m16n8k16.row.col.f32.bf16.bf16.f32 "
                 "{%0,%1,%2,%3}, {%4,%5,%6,%7}, {%8,%9}, {%0,%1,%2,%3};"
                 : "+f"(d[0]), "+f"(d[1]), "+f"(d[2]), "+f"(d[3])
                 : "r"(a[0]), "r"(a[1]), "r"(a[2]), "r"(a[3]), "r"(b0), "r"(b1));
}
__device__ __forceinline__ void ldsm4(uint32_t* r, uint32_t addr) {
    asm volatile("ldmatrix.sync.aligned.m8n8.x4.shared.b16 {%0,%1,%2,%3}, [%4];"
                 : "=r"(r[0]), "=r"(r[1]), "=r"(r[2]), "=r"(r[3]) : "r"(addr));
}

// fast accurate sincos: fp64 range reduction + fp32 poly (~1e-7 abs)
__device__ __forceinline__ void sincos_acc(float a, float* so, float* co) {
    double ad = (double)a;
    double kd = rint(ad * 0.6366197723675814);            // 2/pi
    double r  = fma(-kd, 1.5707963267948966, ad);
    r = fma(-kd, 6.123233995736766e-17, r);
    float rf = (float)r;
    float r2 = rf * rf;
    float sp = fmaf(r2, fmaf(r2, fmaf(r2, fmaf(r2, 2.7557314e-6f, -1.9841249e-4f),
                    8.3333338e-3f), -1.6666667e-1f), 1.0f);
    sp *= rf;
    float cp = fmaf(r2, fmaf(r2, fmaf(r2, fmaf(r2, -2.7557319e-7f, 2.4801587e-5f),
                    -1.3888889e-3f), 4.1666668e-2f), 0.0f);
    cp = fmaf(r2, cp, fmaf(r2, -0.5f, 1.0f));
    int q = ((int)kd) & 3;
    float s, c;
    if (q == 0)      { s =  sp; c =  cp; }
    else if (q == 1) { s =  cp; c = -sp; }
    else if (q == 2) { s = -sp; c = -cp; }
    else             { s = -cp; c =  sp; }
    *so = s; *co = c;
}

// ---------------- routing ----------------
__global__ void k_zero() { if (threadIdx.x < 8) g_cnt[threadIdx.x] = 0; }

__global__ void k_route(const float* __restrict__ pts, float* __restrict__ out) {
    int i = blockIdx.x * blockDim.x + threadIdx.x;
    if (i >= NPTS) return;
    float x = pts[3 * i], y = pts[3 * i + 1], z = pts[3 * i + 2];
    bool fg = (x >= -80.f) && (x <= 80.f) && (y >= -80.f) && (y <= 80.f)
           && (z >= -4.f) && (z <= 44.f);
    if (!fg) {
        out[i] = 0.f;
        out[NPTS + 3 * i] = 0.f; out[NPTS + 3 * i + 1] = 0.f; out[NPTS + 3 * i + 2] = 0.f;
        return;
    }
    int jx = (x > 0.f) ? 1 : 0;
    int iy = (y > 50.f) ? 3 : (y > 0.f) ? 2 : (y > -50.f) ? 1 : 0;
    int e = iy * 2 + jx;
    int pos = atomicAdd(&g_cnt[e], 1);
    g_list[e * NPTS + pos] = i;
}

// ==== weight prep: f32 [K][N] -> bf16 hi/lo transposed [256 n][32 k] chunks ====
__global__ void k_prep(const float* __restrict__ W0, const float* __restrict__ Wpre,
                       const float* __restrict__ Wskip, const float* __restrict__ Wpost,
                       const float* __restrict__ Wf, const float* __restrict__ Wc1) {
    int ch = blockIdx.x;
    int e = ch / CPE, r = ch % CPE;
    const float* src; int K, N, k0;
    if (r < 4)       { src = W0    + (size_t)e * 111 * 256; K = 111; N = 256; k0 = r * 32; }
    else if (r < 28) { int i = (r - 4) >> 3;  src = Wpre  + ((size_t)e * 3 + i) * 65536; K = 256; N = 256; k0 = ((r - 4) & 7) * 32; }
    else if (r < 40) { src = Wskip + (size_t)e * 367 * 256; K = 367; N = 256; k0 = (r - 28) * 32; }
    else if (r < 64) { int i = (r - 40) >> 3; src = Wpost + ((size_t)e * 3 + i) * 65536; K = 256; N = 256; k0 = ((r - 40) & 7) * 32; }
    else if (r < 72) { src = Wf    + (size_t)e * 65536;     K = 256; N = 256; k0 = (r - 64) * 32; }
    else             { src = Wc1   + (size_t)e * 283 * 128; K = 283; N = 128; k0 = (r - 72) * 32; }
    int n = threadIdx.x;   // 0..255
    __nv_bfloat16 hi[32], lo[32];
#pragma unroll 8
    for (int kk = 0; kk < 32; kk++) {
        int k = k0 + kk;
        float v = (k < K && n < N) ? src[(size_t)k * N + n] : 0.f;
        __nv_bfloat16 h = __float2bfloat16(v);
        hi[kk] = h;
        lo[kk] = __float2bfloat16(v - __bfloat162float(h));
    }
    char* dh = (char*)Whi_g + (size_t)ch * 20480 + n * 80;
    char* dl = (char*)Wlo_g + (size_t)ch * 20480 + n * 80;
#pragma unroll
    for (int g = 0; g < 4; g++) {
        *(uint4*)(dh + g * 16) = *(uint4*)&hi[g * 8];
        *(uint4*)(dl + g * 16) = *(uint4*)&lo[g * 8];
    }
}

// ---------------- bulk chunk staging (thread 0 only) ----------------
// Stages global chunk gch into buffer buf; completion tracked on mbar[buf].
__device__ __forceinline__ void stage_bulk(char* smp, int buf, int gch) {
    uint32_t mb = smem_u32(smp + SB_MBAR) + (uint32_t)(buf * 8);
    uint32_t dst = smem_u32(smp + SB_WS) + (uint32_t)(buf * 40960);
    mbar_expect(mb, 40960u);
    bulkcp(dst, (const char*)Whi_g + (size_t)gch * 20480, 20480u, mb);
    bulkcp(dst + 20480u, (const char*)Wlo_g + (size_t)gch * 20480, 20480u, mb);
}

// ---------------- one GEMM layer over a 64-pt tile, 32 warps ----------------
// Warp w: m = w&3 (16 rows), ng = w>>2 (32 cols).
// Chunks are globally contiguous per expert (eb+0..eb+80); lbase is the local
// chunk base of this layer. Staging runs one chunk ahead ACROSS layer bounds.
// mode: 0 relu+writeA ; 1 relu+writeA+density ; 2 writeA no relu ; 3 relu+color (N=128)
__device__ __noinline__ void gemm_layer(char* smp, int eb, int lbase, int nch, int acolb,
                                        int mode, const float* __restrict__ bias, int* ph) {
    const int tid = threadIdx.x;
    const int w = tid >> 5, l = tid & 31;
    const int m = w & 3, ng = w >> 2;
    const int gid = l >> 2, tig = l & 3;
    const bool active = (mode == 3) ? (ng < 4) : true;

    float acc[4][4];
#pragma unroll
    for (int nt = 0; nt < 4; nt++)
#pragma unroll
        for (int j = 0; j < 4; j++) acc[nt][j] = 0.f;

    // ldmatrix lane addresses (x4):
    const uint32_t ah_base = smem_u32(smp + SB_AH)
        + (uint32_t)((m * 16 + (l & 7) + ((l >> 3) & 1) * 8) * 784 + acolb + (l >> 4) * 16);
    const uint32_t al_base = ah_base + (uint32_t)(SB_AL - SB_AH);
    const uint32_t ws_base = smem_u32(smp + SB_WS);
    const uint32_t brow_off = (uint32_t)(((l & 7) + ((l >> 4) & 1) * 8) * 80 + ((l >> 3) & 1) * 16);
    const uint32_t b_p0 = (uint32_t)(ng * 32 * 80) + brow_off;
    const uint32_t mbase = smem_u32(smp + SB_MBAR);

    for (int c = 0; c < nch; c++) {
        int lc = lbase + c;
        int buf = lc & 1;
        __syncthreads();                    // all warps done with buf (lc+1)&1 from chunk lc-1
        if (tid == 0 && lc + 1 <= 80) stage_bulk(smp, (lc + 1) & 1, eb + lc + 1);
        waitp(mbase + (uint32_t)(buf * 8), (uint32_t)(ph[buf] & 1));
        ph[buf]++;
        if (active) {
            uint32_t wb = ws_base + (uint32_t)(buf * 40960);
#pragma unroll
            for (int ks2 = 0; ks2 < 2; ks2++) {
                uint32_t ka = (uint32_t)(c * 64 + ks2 * 32);
                uint32_t ah[4], al[4];
                ldsm4(ah, ah_base + ka);
                ldsm4(al, al_base + ka);
#pragma unroll
                for (int p = 0; p < 2; p++) {
                    uint32_t bh[4], bl[4];
                    uint32_t bo = wb + b_p0 + (uint32_t)(p * 16 * 80 + ks2 * 32);
                    ldsm4(bh, bo);
                    ldsm4(bl, bo + 20480u);
#pragma unroll
                    for (int q = 0; q < 2; q++) {
                        int nt = p * 2 + q;
                        mma16816(acc[nt], ah, bh[2 * q], bh[2 * q + 1]);
                        mma16816(acc[nt], al, bh[2 * q], bh[2 * q + 1]);
                        mma16816(acc[nt], ah, bl[2 * q], bl[2 * q + 1]);
                    }
                }
            }
        }
    }

    __syncthreads();   // all A reads done before in-place writeback
    if (active) {
        float dp[2];
        float cp3[2][3];
        dp[0] = dp[1] = 0.f;
#pragma unroll
        for (int hf = 0; hf < 2; hf++) { cp3[hf][0] = 0.f; cp3[hf][1] = 0.f; cp3[hf][2] = 0.f; }
        float* WdS  = (float*)(smp + SB_WD);
        float* Wc2S = (float*)(smp + SB_WC2);
#pragma unroll
        for (int nt = 0; nt < 4; nt++) {
            int c0 = ng * 32 + nt * 8 + 2 * tig;
            float b0v = __ldg(bias + c0), b1v = __ldg(bias + c0 + 1);
            float v0 = acc[nt][0] + b0v;
            float v1 = acc[nt][1] + b1v;
            float v2 = acc[nt][2] + b0v;
            float v3 = acc[nt][3] + b1v;
            if (mode != 2) {
                v0 = fmaxf(v0, 0.f); v1 = fmaxf(v1, 0.f);
                v2 = fmaxf(v2, 0.f); v3 = fmaxf(v3, 0.f);
            }
            if (mode == 1) {
                dp[0] += v0 * WdS[c0] + v1 * WdS[c0 + 1];
                dp[1] += v2 * WdS[c0] + v3 * WdS[c0 + 1];
            }
            if (mode == 3) {
#pragma unroll
                for (int chn = 0; chn < 3; chn++) {
                    cp3[0][chn] += v0 * Wc2S[c0 * 3 + chn] + v1 * Wc2S[(c0 + 1) * 3 + chn];
                    cp3[1][chn] += v2 * Wc2S[c0 * 3 + chn] + v3 * Wc2S[(c0 + 1) * 3 + chn];
                }
            } else {
                uint32_t off0 = (uint32_t)((m * 16 + gid) * 784 + c0 * 2);
                uint32_t off1 = off0 + 8u * 784u;
                __nv_bfloat16 h0 = __float2bfloat16(v0), h1 = __float2bfloat16(v1);
                __nv_bfloat16 h2 = __float2bfloat16(v2), h3 = __float2bfloat16(v3);
                __nv_bfloat162 H0 = __halves2bfloat162(h0, h1);
                __nv_bfloat162 H1 = __halves2bfloat162(h2, h3);
                __nv_bfloat162 L0 = __halves2bfloat162(
                    __float2bfloat16(v0 - __bfloat162float(h0)),
                    __float2bfloat16(v1 - __bfloat162float(h1)));
                __nv_bfloat162 L1 = __halves2bfloat162(
                    __float2bfloat16(v2 - __bfloat162float(h2)),
                    __float2bfloat16(v3 - __bfloat162float(h3)));
                *(uint32_t*)(smp + SB_AH + off0) = *(uint32_t*)&H0;
                *(uint32_t*)(smp + SB_AH + off1) = *(uint32_t*)&H1;
                *(uint32_t*)(smp + SB_AL + off0) = *(uint32_t*)&L0;
                *(uint32_t*)(smp + SB_AL + off1) = *(uint32_t*)&L1;
            }
        }
        if (mode == 1) {
#pragma unroll
            for (int hf = 0; hf < 2; hf++) {
                float s = dp[hf];
                s += __shfl_xor_sync(0xffffffffu, s, 1);
                s += __shfl_xor_sync(0xffffffffu, s, 2);
                if (tig == 0)
                    ((float*)(smp + SB_DENSP))[ng * 64 + m * 16 + hf * 8 + gid] = s;
            }
        }
        if (mode == 3) {
#pragma unroll
            for (int hf = 0; hf < 2; hf++)
#pragma unroll
                for (int chn = 0; chn < 3; chn++) {
                    float s = cp3[hf][chn];
                    s += __shfl_xor_sync(0xffffffffu, s, 1);
                    s += __shfl_xor_sync(0xffffffffu, s, 2);
                    if (tig == 0)
                        ((float*)(smp + SB_COLP))[(ng * 64 + m * 16 + hf * 8 + gid) * 3 + chn] = s;
                }
        }
    }
    __syncthreads();
}

// smem A-tile store (bf16 hi + lo)
__device__ __forceinline__ void a_store(char* smp, int p, int col, float v) {
    uint32_t off = (uint32_t)(p * 784 + col * 2);
    __nv_bfloat16 h = __float2bfloat16(v);
    *(__nv_bfloat16*)(smp + SB_AH + off) = h;
    *(__nv_bfloat16*)(smp + SB_AL + off) = __float2bfloat16(v - __bfloat162float(h));
}

// ---------------- main MLP kernel ----------------
__global__ void __launch_bounds__(NTHR, 1) k_mlp(
    const float* __restrict__ pts, const float* __restrict__ vds,
    const int* __restrict__ aidx, const float* __restrict__ app,
    const float* __restrict__ b0, const float* __restrict__ bpre,
    const float* __restrict__ bskip, const float* __restrict__ bpost,
    const float* __restrict__ Wd, const float* __restrict__ bd,
    const float* __restrict__ bf, const float* __restrict__ bc1,
    const float* __restrict__ Wc2, const float* __restrict__ bc2,
    float* __restrict__ out) {
    extern __shared__ char smp[];
    const int tid = threadIdx.x;

    if (tid == 0) {
        mbar_init(smem_u32(smp + SB_MBAR), 1u);
        mbar_init(smem_u32(smp + SB_MBAR) + 8u, 1u);
    }
    int ph[2]; ph[0] = 0; ph[1] = 0;

    int cnt8[8], tb[8], tot = 0;
#pragma unroll
    for (int e8 = 0; e8 < 8; e8++) {
        cnt8[e8] = g_cnt[e8]; tb[e8] = tot;
        tot += (cnt8[e8] + TILE - 1) / TILE;
    }
    int* gidx = (int*)(smp + SB_GIDX);
    float* WdS  = (float*)(smp + SB_WD);
    float* Wc2S = (float*)(smp + SB_WC2);
    __syncthreads();   // mbar init visible

    for (int tile = blockIdx.x; tile < tot; tile += gridDim.x) {
        int e = 0;
#pragma unroll
        for (int e8 = 1; e8 < 8; e8++) if (tile >= tb[e8]) e = e8;
        const int base = (tile - tb[e]) * TILE;
        const int npts = min(TILE, cnt8[e] - base);
        const int eb = e * CPE;

        // stage chunk 0 early: its latency hides under setup below
        if (tid == 0) stage_bulk(smp, 0, eb + 0);

        // zero A hi+lo (100352 B = 6272 uint4)
        for (int u = tid; u < 6272; u += NTHR)
            ((uint4*)(smp + SB_AH))[u] = make_uint4(0, 0, 0, 0);
        if (tid < 256) WdS[tid] = Wd[e * 256 + tid];
        if (tid >= 256 && tid < 643) {
            int j = tid - 256;
            Wc2S[j] = (j < 384) ? Wc2[e * 384 + j] : bc2[e * 3 + (j - 384)];
        }
        __syncthreads();

        // posenc + appearance -> A cols 256..366 (16 threads per point)
        {
            int pt = tid >> 4, q = tid & 15;
            if (pt < npts) {
                int g = g_list[e * NPTS + base + pt];
                float px = pts[3 * g], py = pts[3 * g + 1], pz = pts[3 * g + 2];
                if (q == 0) {
                    gidx[pt] = g;
                    a_store(smp, pt, 256, px); a_store(smp, pt, 257, py); a_store(smp, pt, 258, pz);
                }
                if (q < 10) {
                    float f = (float)exp2((double)q * (10.0 / 9.0));
                    int r = 256 + 3 + 6 * q;
                    float s, c;
                    sincos_acc(f * px, &s, &c); a_store(smp, pt, r + 0, s); a_store(smp, pt, r + 3, c);
                    sincos_acc(f * py, &s, &c); a_store(smp, pt, r + 1, s); a_store(smp, pt, r + 4, c);
                    sincos_acc(f * pz, &s, &c); a_store(smp, pt, r + 2, s); a_store(smp, pt, r + 5, c);
                }
                int ai = aidx[g];
                const float* a = app + ((size_t)e * 1000 + ai) * 48;
                for (int j = q; j < 48; j += 16) a_store(smp, pt, 256 + 63 + j, a[j]);
            } else if (q == 0) gidx[pt] = 0;
        }

        // trunk (chunks 0..80 globally contiguous; staging pipelined across layers)
        gemm_layer(smp, eb, 0, 4, 512, 0, b0 + e * 256, ph);              // W0
        for (int i = 0; i < 3; i++)
            gemm_layer(smp, eb, 4 + 8 * i, 8, 0, 0, bpre + (e * 3 + i) * 256, ph);
        gemm_layer(smp, eb, 28, 12, 0, 0, bskip + e * 256, ph);           // skip (K=384)

        // dir-enc overwrites x0 region cols 256..287 (also zero stale 283..287)
        {
            int pt = tid >> 4, q = tid & 15;
            if (pt < npts) {
                int g = gidx[pt];
                float vx = vds[3 * g], vy = vds[3 * g + 1], vz = vds[3 * g + 2];
                if (q < 4) {
                    float f = (float)exp2((double)q * (4.0 / 3.0));
                    int r = 256 + 3 + 6 * q;
                    float s, c;
                    sincos_acc(f * vx, &s, &c); a_store(smp, pt, r + 0, s); a_store(smp, pt, r + 3, c);
                    sincos_acc(f * vy, &s, &c); a_store(smp, pt, r + 1, s); a_store(smp, pt, r + 4, c);
                    sincos_acc(f * vz, &s, &c); a_store(smp, pt, r + 2, s); a_store(smp, pt, r + 5, c);
                } else if (q == 4) {
                    a_store(smp, pt, 256, vx); a_store(smp, pt, 257, vy); a_store(smp, pt, 258, vz);
                } else if (q == 5) {
                    for (int j = 283; j < 288; j++) a_store(smp, pt, j, 0.f);
                }
            }
        }

        for (int i = 0; i < 3; i++)
            gemm_layer(smp, eb, 40 + 8 * i, 8, 0, (i == 2) ? 1 : 0, bpost + (e * 3 + i) * 256, ph);

        // density finalize
        if (tid < 64) {
            float* dps = (float*)(smp + SB_DENSP);
            float s = bd[e];
#pragma unroll
            for (int ngx = 0; ngx < 8; ngx++) s += dps[ngx * 64 + tid];
            if (tid < npts) out[gidx[tid]] = fmaxf(s, 0.f);
        }

        gemm_layer(smp, eb, 64, 8, 0, 2, bf + e * 256, ph);               // feature
        gemm_layer(smp, eb, 72, 9, 0, 3, bc1 + e * 128, ph);              // color hidden

        // color finalize
        if (tid < 192) {
            int pt = tid / 3, chn = tid - 3 * pt;
            float* cps = (float*)(smp + SB_COLP);
            float s = Wc2S[384 + chn];
#pragma unroll
            for (int ngx = 0; ngx < 4; ngx++) s += cps[(ngx * 64 + pt) * 3 + chn];
            if (pt < npts) out[NPTS + 3 * gidx[pt] + chn] = 1.f / (1.f + expf(-s));
        }
        __syncthreads();   // smem reused next tile
    }
}

// ---------------- launch ----------------
extern "C" void kernel_launch(void* const* d_in, const int* in_sizes, int n_in,
                              void* d_out, int out_size) {
    const float* pts   = (const float*)d_in[0];
    const float* vds   = (const float*)d_in[1];
    const int*   aidx  = (const int*)d_in[2];
    const float* app   = (const float*)d_in[3];
    const float* W0    = (const float*)d_in[4];
    const float* b0    = (const float*)d_in[5];
    const float* Wpre  = (const float*)d_in[6];
    const float* bpre  = (const float*)d_in[7];
    const float* Wskip = (const float*)d_in[8];
    const float* bskip = (const float*)d_in[9];
    const float* Wpost = (const float*)d_in[10];
    const float* bpost = (const float*)d_in[11];
    const float* Wd    = (const float*)d_in[12];
    const float* bd    = (const float*)d_in[13];
    const float* Wf    = (const float*)d_in[14];
    const float* bf    = (const float*)d_in[15];
    const float* Wc1   = (const float*)d_in[16];
    const float* bc1   = (const float*)d_in[17];
    const float* Wc2   = (const float*)d_in[18];
    const float* bc2   = (const float*)d_in[19];
    float* out = (float*)d_out;

    static bool attr_done = false;
    if (!attr_done) {
        cudaFuncSetAttribute(k_mlp, cudaFuncAttributeMaxDynamicSharedMemorySize, SMEM_BYTES);
        attr_done = true;
    }

    k_prep<<<NCHUNKS, 256>>>(W0, Wpre, Wskip, Wpost, Wf, Wc1);
    k_zero<<<1, 32>>>();
    k_route<<<NPTS / 256, 256>>>(pts, out);
    k_mlp<<<NCTA, NTHR, SMEM_BYTES>>>(pts, vds, aidx, app, b0, bpre, bskip, bpost,
                                      Wd, bd, bf, bc1, Wc2, bc2, out);
}

// round 13
// speedup vs baseline: 1.1124x; 1.0345x over previous
#include <cuda_runtime.h>
#include <cuda_bf16.h>
#include <math.h>
#include <stdint.h>

#define NPTS 32768
#define TILE 64
#define NTHR 1024
#define NCTA 148
#define CPE  81
#define NCHUNKS (8 * CPE)

__device__ int g_cnt[8];
__device__ int g_list[8 * NPTS];
__device__ __align__(16) __nv_bfloat16 Whi_g[(size_t)NCHUNKS * 10240];
__device__ __align__(16) __nv_bfloat16 Wlo_g[(size_t)NCHUNKS * 10240];

// ---- smem layout (bytes) ----
#define SB_WS    0                /* 3 x 40960 (hi 20480 + lo 20480) ring */
#define SB_AH    122880           /* 64 x 784 = 50176 */
#define SB_AL    173056           /* 50176 */
#define SB_GIDX  223232           /* 256 */
#define SB_WD    223488           /* 1024 */
#define SB_WC2   224512           /* 1552 */
#define SB_DENSP 226064           /* 2048 */
#define SB_COLP  228112           /* 3072 */
#define SB_MBAR  231184           /* full[3] @0,8,16 ; cons[3] @24,32,40 */
#define SMEM_BYTES 231232

// ---------------- helpers ----------------
__device__ __forceinline__ uint32_t smem_u32(const void* p) {
    uint32_t a;
    asm("{ .reg .u64 t; cvta.to.shared.u64 t, %1; cvt.u32.u64 %0, t; }" : "=r"(a) : "l"(p));
    return a;
}
__device__ __forceinline__ void mbar_init(uint32_t mb, uint32_t n) {
    asm volatile("mbarrier.init.shared.b64 [%0], %1;" :: "r"(mb), "r"(n) : "memory");
}
__device__ __forceinline__ void mbar_expect(uint32_t mb, uint32_t bytes) {
    asm volatile("mbarrier.arrive.expect_tx.shared.b64 _, [%0], %1;" :: "r"(mb), "r"(bytes) : "memory");
}
__device__ __forceinline__ void mbar_arrive(uint32_t mb) {
    asm volatile("mbarrier.arrive.shared.b64 _, [%0];" :: "r"(mb) : "memory");
}
__device__ __forceinline__ void waitp(uint32_t mb, uint32_t par) {
    uint32_t done;
    asm volatile("{ .reg .pred p; mbarrier.try_wait.parity.acquire.cta.shared::cta.b64 p, [%1], %2; selp.b32 %0, 1, 0, p; }"
                 : "=r"(done) : "r"(mb), "r"(par) : "memory");
    while (!done) {
        asm volatile("{ .reg .pred p; mbarrier.try_wait.parity.acquire.cta.shared::cta.b64 p, [%1], %2, 0x989680; selp.b32 %0, 1, 0, p; }"
                     : "=r"(done) : "r"(mb), "r"(par) : "memory");
    }
}
__device__ __forceinline__ void bulkcp(uint32_t dst, const void* src, uint32_t bytes, uint32_t mb) {
    asm volatile("cp.async.bulk.shared::cluster.global.mbarrier::complete_tx::bytes [%0], [%1], %2, [%3];"
                 :: "r"(dst), "l"(src), "r"(bytes), "r"(mb) : "memory");
}
__device__ __forceinline__ void mma16816(float* d, const uint32_t* a, uint32_t b0, uint32_t b1) {
    asm volatile("mma.sync.aligned.m16n8k16.row.col.f32.bf16.bf16.f32 "
                 "{%0,%1,%2,%3}, {%4,%5,%6,%7}, {%8,%9}, {%0,%1,%2,%3};"
                 : "+f"(d[0]), "+f"(d[1]), "+f"(d[2]), "+f"(d[3])
                 : "r"(a[0]), "r"(a[1]), "r"(a[2]), "r"(a[3]), "r"(b0), "r"(b1));
}
__device__ __forceinline__ void ldsm4(uint32_t* r, uint32_t addr) {
    asm volatile("ldmatrix.sync.aligned.m8n8.x4.shared.b16 {%0,%1,%2,%3}, [%4];"
                 : "=r"(r[0]), "=r"(r[1]), "=r"(r[2]), "=r"(r[3]) : "r"(addr));
}

// fast accurate sincos: fp64 range reduction + fp32 poly (~1e-7 abs)
__device__ __forceinline__ void sincos_acc(float a, float* so, float* co) {
    double ad = (double)a;
    double kd = rint(ad * 0.6366197723675814);            // 2/pi
    double r  = fma(-kd, 1.5707963267948966, ad);
    r = fma(-kd, 6.123233995736766e-17, r);
    float rf = (float)r;
    float r2 = rf * rf;
    float sp = fmaf(r2, fmaf(r2, fmaf(r2, fmaf(r2, 2.7557314e-6f, -1.9841249e-4f),
                    8.3333338e-3f), -1.6666667e-1f), 1.0f);
    sp *= rf;
    float cp = fmaf(r2, fmaf(r2, fmaf(r2, fmaf(r2, -2.7557319e-7f, 2.4801587e-5f),
                    -1.3888889e-3f), 4.1666668e-2f), 0.0f);
    cp = fmaf(r2, cp, fmaf(r2, -0.5f, 1.0f));
    int q = ((int)kd) & 3;
    float s, c;
    if (q == 0)      { s =  sp; c =  cp; }
    else if (q == 1) { s =  cp; c = -sp; }
    else if (q == 2) { s = -sp; c = -cp; }
    else             { s = -cp; c =  sp; }
    *so = s; *co = c;
}

// ---------------- routing ----------------
__global__ void k_zero() { if (threadIdx.x < 8) g_cnt[threadIdx.x] = 0; }

__global__ void k_route(const float* __restrict__ pts, float* __restrict__ out) {
    int i = blockIdx.x * blockDim.x + threadIdx.x;
    if (i >= NPTS) return;
    float x = pts[3 * i], y = pts[3 * i + 1], z = pts[3 * i + 2];
    bool fg = (x >= -80.f) && (x <= 80.f) && (y >= -80.f) && (y <= 80.f)
           && (z >= -4.f) && (z <= 44.f);
    if (!fg) {
        out[i] = 0.f;
        out[NPTS + 3 * i] = 0.f; out[NPTS + 3 * i + 1] = 0.f; out[NPTS + 3 * i + 2] = 0.f;
        return;
    }
    int jx = (x > 0.f) ? 1 : 0;
    int iy = (y > 50.f) ? 3 : (y > 0.f) ? 2 : (y > -50.f) ? 1 : 0;
    int e = iy * 2 + jx;
    int pos = atomicAdd(&g_cnt[e], 1);
    g_list[e * NPTS + pos] = i;
}

// ==== weight prep: f32 [K][N] -> bf16 hi/lo transposed [256 n][32 k] chunks ====
__global__ void k_prep(const float* __restrict__ W0, const float* __restrict__ Wpre,
                       const float* __restrict__ Wskip, const float* __restrict__ Wpost,
                       const float* __restrict__ Wf, const float* __restrict__ Wc1) {
    int ch = blockIdx.x;
    int e = ch / CPE, r = ch % CPE;
    const float* src; int K, N, k0;
    if (r < 4)       { src = W0    + (size_t)e * 111 * 256; K = 111; N = 256; k0 = r * 32; }
    else if (r < 28) { int i = (r - 4) >> 3;  src = Wpre  + ((size_t)e * 3 + i) * 65536; K = 256; N = 256; k0 = ((r - 4) & 7) * 32; }
    else if (r < 40) { src = Wskip + (size_t)e * 367 * 256; K = 367; N = 256; k0 = (r - 28) * 32; }
    else if (r < 64) { int i = (r - 40) >> 3; src = Wpost + ((size_t)e * 3 + i) * 65536; K = 256; N = 256; k0 = ((r - 40) & 7) * 32; }
    else if (r < 72) { src = Wf    + (size_t)e * 65536;     K = 256; N = 256; k0 = (r - 64) * 32; }
    else             { src = Wc1   + (size_t)e * 283 * 128; K = 283; N = 128; k0 = (r - 72) * 32; }
    int n = threadIdx.x;   // 0..255
    __nv_bfloat16 hi[32], lo[32];
#pragma unroll 8
    for (int kk = 0; kk < 32; kk++) {
        int k = k0 + kk;
        float v = (k < K && n < N) ? src[(size_t)k * N + n] : 0.f;
        __nv_bfloat16 h = __float2bfloat16(v);
        hi[kk] = h;
        lo[kk] = __float2bfloat16(v - __bfloat162float(h));
    }
    char* dh = (char*)Whi_g + (size_t)ch * 20480 + n * 80;
    char* dl = (char*)Wlo_g + (size_t)ch * 20480 + n * 80;
#pragma unroll
    for (int g = 0; g < 4; g++) {
        *(uint4*)(dh + g * 16) = *(uint4*)&hi[g * 8];
        *(uint4*)(dl + g * 16) = *(uint4*)&lo[g * 8];
    }
}

// ---------------- producer staging (thread 0 only) ----------------
// Stage ordinal *sgp (global, sequential) -> buffer sg%3. Waits buffer recycle
// via cons[b] parity derived from the stage ordinal.
__device__ __forceinline__ void stage3(char* smp, int* sgp, int gch) {
    int s = *sgp;
    int b = s % 3;
    uint32_t mbase = smem_u32(smp + SB_MBAR);
    if (s >= 3) waitp(mbase + 24u + (uint32_t)(b * 8), (uint32_t)(((s / 3) - 1) & 1));
    uint32_t full = mbase + (uint32_t)(b * 8);
    uint32_t dst = smem_u32(smp + SB_WS) + (uint32_t)(b * 40960);
    mbar_expect(full, 40960u);
    bulkcp(dst, (const char*)Whi_g + (size_t)gch * 20480, 20480u, full);
    bulkcp(dst + 20480u, (const char*)Wlo_g + (size_t)gch * 20480, 20480u, full);
    *sgp = s + 1;
}

// ---------------- one GEMM layer over a 64-pt tile, 32 warps ----------------
// Warp w: m = w&3 (16 rows), ng = w>>2 (32 cols). Ring-desynchronized mainloop:
// no per-chunk block barrier; warps drift up to 3 chunks within a layer.
// mode: 0 relu+writeA ; 1 relu+writeA+density ; 2 writeA no relu ; 3 relu+color (N=128)
__device__ __noinline__ void gemm_layer(char* smp, int eb, int lbase, int nch, int acolb,
                                        int mode, const float* __restrict__ bias,
                                        int* tcp, int* sgp) {
    const int tid = threadIdx.x;
    const int w = tid >> 5, l = tid & 31;
    const int m = w & 3, ng = w >> 2;
    const int gid = l >> 2, tig = l & 3;
    const bool active = (mode == 3) ? (ng < 4) : true;

    float acc[4][4];
#pragma unroll
    for (int nt = 0; nt < 4; nt++)
#pragma unroll
        for (int j = 0; j < 4; j++) acc[nt][j] = 0.f;

    const uint32_t ah_base = smem_u32(smp + SB_AH)
        + (uint32_t)((m * 16 + (l & 7) + ((l >> 3) & 1) * 8) * 784 + acolb + (l >> 4) * 16);
    const uint32_t al_base = ah_base + (uint32_t)(SB_AL - SB_AH);
    const uint32_t ws_base = smem_u32(smp + SB_WS);
    const uint32_t brow_off = (uint32_t)(((l & 7) + ((l >> 4) & 1) * 8) * 80 + ((l >> 3) & 1) * 16);
    const uint32_t b_p0 = (uint32_t)(ng * 32 * 80) + brow_off;
    const uint32_t mbase = smem_u32(smp + SB_MBAR);

    int tc = *tcp;
    for (int c = 0; c < nch; c++) {
        int lc = lbase + c;
        int buf = lc % 3;                 // == tc % 3 (81 chunks/tile, divisible by 3)
        waitp(mbase + (uint32_t)(buf * 8), (uint32_t)((tc / 3) & 1));
        if (active) {
            uint32_t wb = ws_base + (uint32_t)(buf * 40960);
#pragma unroll
            for (int ks2 = 0; ks2 < 2; ks2++) {
                uint32_t ka = (uint32_t)(c * 64 + ks2 * 32);
                uint32_t ah[4], al[4];
                ldsm4(ah, ah_base + ka);
                ldsm4(al, al_base + ka);
#pragma unroll
                for (int p = 0; p < 2; p++) {
                    uint32_t bh[4], bl[4];
                    uint32_t bo = wb + b_p0 + (uint32_t)(p * 16 * 80 + ks2 * 32);
                    ldsm4(bh, bo);
                    ldsm4(bl, bo + 20480u);
#pragma unroll
                    for (int q = 0; q < 2; q++) {
                        int nt = p * 2 + q;
                        mma16816(acc[nt], ah, bh[2 * q], bh[2 * q + 1]);
                        mma16816(acc[nt], al, bh[2 * q], bh[2 * q + 1]);
                        mma16816(acc[nt], ah, bl[2 * q], bl[2 * q + 1]);
                    }
                }
            }
        }
        __syncwarp();
        if (l == 0) mbar_arrive(mbase + 24u + (uint32_t)(buf * 8));
        if (tid == 0 && lc + 3 <= 80) stage3(smp, sgp, eb + lc + 3);
        tc++;
    }
    *tcp = tc;

    __syncthreads();   // all A reads done before in-place writeback
    if (active) {
        float dp[2];
        float cp3[2][3];
        dp[0] = dp[1] = 0.f;
#pragma unroll
        for (int hf = 0; hf < 2; hf++) { cp3[hf][0] = 0.f; cp3[hf][1] = 0.f; cp3[hf][2] = 0.f; }
        float* WdS  = (float*)(smp + SB_WD);
        float* Wc2S = (float*)(smp + SB_WC2);
#pragma unroll
        for (int nt = 0; nt < 4; nt++) {
            int c0 = ng * 32 + nt * 8 + 2 * tig;
            float b0v = __ldg(bias + c0), b1v = __ldg(bias + c0 + 1);
            float v0 = acc[nt][0] + b0v;
            float v1 = acc[nt][1] + b1v;
            float v2 = acc[nt][2] + b0v;
            float v3 = acc[nt][3] + b1v;
            if (mode != 2) {
                v0 = fmaxf(v0, 0.f); v1 = fmaxf(v1, 0.f);
                v2 = fmaxf(v2, 0.f); v3 = fmaxf(v3, 0.f);
            }
            if (mode == 1) {
                dp[0] += v0 * WdS[c0] + v1 * WdS[c0 + 1];
                dp[1] += v2 * WdS[c0] + v3 * WdS[c0 + 1];
            }
            if (mode == 3) {
#pragma unroll
                for (int chn = 0; chn < 3; chn++) {
                    cp3[0][chn] += v0 * Wc2S[c0 * 3 + chn] + v1 * Wc2S[(c0 + 1) * 3 + chn];
                    cp3[1][chn] += v2 * Wc2S[c0 * 3 + chn] + v3 * Wc2S[(c0 + 1) * 3 + chn];
                }
            } else {
                uint32_t off0 = (uint32_t)((m * 16 + gid) * 784 + c0 * 2);
                uint32_t off1 = off0 + 8u * 784u;
                __nv_bfloat16 h0 = __float2bfloat16(v0), h1 = __float2bfloat16(v1);
                __nv_bfloat16 h2 = __float2bfloat16(v2), h3 = __float2bfloat16(v3);
                __nv_bfloat162 H0 = __halves2bfloat162(h0, h1);
                __nv_bfloat162 H1 = __halves2bfloat162(h2, h3);
                __nv_bfloat162 L0 = __halves2bfloat162(
                    __float2bfloat16(v0 - __bfloat162float(h0)),
                    __float2bfloat16(v1 - __bfloat162float(h1)));
                __nv_bfloat162 L1 = __halves2bfloat162(
                    __float2bfloat16(v2 - __bfloat162float(h2)),
                    __float2bfloat16(v3 - __bfloat162float(h3)));
                *(uint32_t*)(smp + SB_AH + off0) = *(uint32_t*)&H0;
                *(uint32_t*)(smp + SB_AH + off1) = *(uint32_t*)&H1;
                *(uint32_t*)(smp + SB_AL + off0) = *(uint32_t*)&L0;
                *(uint32_t*)(smp + SB_AL + off1) = *(uint32_t*)&L1;
            }
        }
        if (mode == 1) {
#pragma unroll
            for (int hf = 0; hf < 2; hf++) {
                float s = dp[hf];
                s += __shfl_xor_sync(0xffffffffu, s, 1);
                s += __shfl_xor_sync(0xffffffffu, s, 2);
                if (tig == 0)
                    ((float*)(smp + SB_DENSP))[ng * 64 + m * 16 + hf * 8 + gid] = s;
            }
        }
        if (mode == 3) {
#pragma unroll
            for (int hf = 0; hf < 2; hf++)
#pragma unroll
                for (int chn = 0; chn < 3; chn++) {
                    float s = cp3[hf][chn];
                    s += __shfl_xor_sync(0xffffffffu, s, 1);
                    s += __shfl_xor_sync(0xffffffffu, s, 2);
                    if (tig == 0)
                        ((float*)(smp + SB_COLP))[(ng * 64 + m * 16 + hf * 8 + gid) * 3 + chn] = s;
                }
        }
    }
    __syncthreads();
}

// smem A-tile store (bf16 hi + lo)
__device__ __forceinline__ void a_store(char* smp, int p, int col, float v) {
    uint32_t off = (uint32_t)(p * 784 + col * 2);
    __nv_bfloat16 h = __float2bfloat16(v);
    *(__nv_bfloat16*)(smp + SB_AH + off) = h;
    *(__nv_bfloat16*)(smp + SB_AL + off) = __float2bfloat16(v - __bfloat162float(h));
}

// ---------------- main MLP kernel ----------------
__global__ void __launch_bounds__(NTHR, 1) k_mlp(
    const float* __restrict__ pts, const float* __restrict__ vds,
    const int* __restrict__ aidx, const float* __restrict__ app,
    const float* __restrict__ b0, const float* __restrict__ bpre,
    const float* __restrict__ bskip, const float* __restrict__ bpost,
    const float* __restrict__ Wd, const float* __restrict__ bd,
    const float* __restrict__ bf, const float* __restrict__ bc1,
    const float* __restrict__ Wc2, const float* __restrict__ bc2,
    float* __restrict__ out) {
    extern __shared__ char smp[];
    const int tid = threadIdx.x;

    if (tid == 0) {
        uint32_t mbase = smem_u32(smp + SB_MBAR);
        for (int i = 0; i < 3; i++) {
            mbar_init(mbase + (uint32_t)(i * 8), 1u);        // full: tx-based
            mbar_init(mbase + 24u + (uint32_t)(i * 8), 32u); // cons: 32 warp arrivals
        }
    }
    int tcg = 0;   // global chunk counter (per thread)
    int sg  = 0;   // global stage counter (thread 0 only)

    int cnt8[8], tb[8], tot = 0;
#pragma unroll
    for (int e8 = 0; e8 < 8; e8++) {
        cnt8[e8] = g_cnt[e8]; tb[e8] = tot;
        tot += (cnt8[e8] + TILE - 1) / TILE;
    }
    int* gidx = (int*)(smp + SB_GIDX);
    float* WdS  = (float*)(smp + SB_WD);
    float* Wc2S = (float*)(smp + SB_WC2);
    __syncthreads();   // mbar init visible

    for (int tile = blockIdx.x; tile < tot; tile += gridDim.x) {
        int e = 0;
#pragma unroll
        for (int e8 = 1; e8 < 8; e8++) if (tile >= tb[e8]) e = e8;
        const int base = (tile - tb[e]) * TILE;
        const int npts = min(TILE, cnt8[e] - base);
        const int eb = e * CPE;

        // stage chunks 0..2: latency hides under tile setup below
        if (tid == 0) {
            stage3(smp, &sg, eb + 0);
            stage3(smp, &sg, eb + 1);
            stage3(smp, &sg, eb + 2);
        }

        // zero A hi+lo (100352 B = 6272 uint4)
        for (int u = tid; u < 6272; u += NTHR)
            ((uint4*)(smp + SB_AH))[u] = make_uint4(0, 0, 0, 0);
        if (tid < 256) WdS[tid] = Wd[e * 256 + tid];
        if (tid >= 256 && tid < 643) {
            int j = tid - 256;
            Wc2S[j] = (j < 384) ? Wc2[e * 384 + j] : bc2[e * 3 + (j - 384)];
        }
        __syncthreads();

        // posenc + appearance -> A cols 256..366 (16 threads per point)
        {
            int pt = tid >> 4, q = tid & 15;
            if (pt < npts) {
                int g = g_list[e * NPTS + base + pt];
                float px = pts[3 * g], py = pts[3 * g + 1], pz = pts[3 * g + 2];
                if (q == 0) {
                    gidx[pt] = g;
                    a_store(smp, pt, 256, px); a_store(smp, pt, 257, py); a_store(smp, pt, 258, pz);
                }
                if (q < 10) {
                    float f = (float)exp2((double)q * (10.0 / 9.0));
                    int r = 256 + 3 + 6 * q;
                    float s, c;
                    sincos_acc(f * px, &s, &c); a_store(smp, pt, r + 0, s); a_store(smp, pt, r + 3, c);
                    sincos_acc(f * py, &s, &c); a_store(smp, pt, r + 1, s); a_store(smp, pt, r + 4, c);
                    sincos_acc(f * pz, &s, &c); a_store(smp, pt, r + 2, s); a_store(smp, pt, r + 5, c);
                }
                int ai = aidx[g];
                const float* a = app + ((size_t)e * 1000 + ai) * 48;
                for (int j = q; j < 48; j += 16) a_store(smp, pt, 256 + 63 + j, a[j]);
            } else if (q == 0) gidx[pt] = 0;
        }
        __syncthreads();

        // trunk (chunks 0..80 globally contiguous; ring staging pipelined across layers)
        gemm_layer(smp, eb, 0, 4, 512, 0, b0 + e * 256, &tcg, &sg);       // W0
        for (int i = 0; i < 3; i++)
            gemm_layer(smp, eb, 4 + 8 * i, 8, 0, 0, bpre + (e * 3 + i) * 256, &tcg, &sg);
        gemm_layer(smp, eb, 28, 12, 0, 0, bskip + e * 256, &tcg, &sg);    // skip (K=384)

        // dir-enc overwrites x0 region cols 256..287 (also zero stale 283..287)
        {
            int pt = tid >> 4, q = tid & 15;
            if (pt < npts) {
                int g = gidx[pt];
                float vx = vds[3 * g], vy = vds[3 * g + 1], vz = vds[3 * g + 2];
                if (q < 4) {
                    float f = (float)exp2((double)q * (4.0 / 3.0));
                    int r = 256 + 3 + 6 * q;
                    float s, c;
                    sincos_acc(f * vx, &s, &c); a_store(smp, pt, r + 0, s); a_store(smp, pt, r + 3, c);
                    sincos_acc(f * vy, &s, &c); a_store(smp, pt, r + 1, s); a_store(smp, pt, r + 4, c);
                    sincos_acc(f * vz, &s, &c); a_store(smp, pt, r + 2, s); a_store(smp, pt, r + 5, c);
                } else if (q == 4) {
                    a_store(smp, pt, 256, vx); a_store(smp, pt, 257, vy); a_store(smp, pt, 258, vz);
                } else if (q == 5) {
                    for (int j = 283; j < 288; j++) a_store(smp, pt, j, 0.f);
                }
            }
        }

        for (int i = 0; i < 3; i++)
            gemm_layer(smp, eb, 40 + 8 * i, 8, 0, (i == 2) ? 1 : 0, bpost + (e * 3 + i) * 256, &tcg, &sg);

        // density finalize
        if (tid < 64) {
            float* dps = (float*)(smp + SB_DENSP);
            float s = bd[e];
#pragma unroll
            for (int ngx = 0; ngx < 8; ngx++) s += dps[ngx * 64 + tid];
            if (tid < npts) out[gidx[tid]] = fmaxf(s, 0.f);
        }

        gemm_layer(smp, eb, 64, 8, 0, 2, bf + e * 256, &tcg, &sg);        // feature
        gemm_layer(smp, eb, 72, 9, 0, 3, bc1 + e * 128, &tcg, &sg);       // color hidden

        // color finalize
        if (tid < 192) {
            int pt = tid / 3, chn = tid - 3 * pt;
            float* cps = (float*)(smp + SB_COLP);
            float s = Wc2S[384 + chn];
#pragma unroll
            for (int ngx = 0; ngx < 4; ngx++) s += cps[(ngx * 64 + pt) * 3 + chn];
            if (pt < npts) out[NPTS + 3 * gidx[pt] + chn] = 1.f / (1.f + expf(-s));
        }
        __syncthreads();   // smem reused next tile
    }
}

// ---------------- launch ----------------
extern "C" void kernel_launch(void* const* d_in, const int* in_sizes, int n_in,
                              void* d_out, int out_size) {
    const float* pts   = (const float*)d_in[0];
    const float* vds   = (const float*)d_in[1];
    const int*   aidx  = (const int*)d_in[2];
    const float* app   = (const float*)d_in[3];
    const float* W0    = (const float*)d_in[4];
    const float* b0    = (const float*)d_in[5];
    const float* Wpre  = (const float*)d_in[6];
    const float* bpre  = (const float*)d_in[7];
    const float* Wskip = (const float*)d_in[8];
    const float* bskip = (const float*)d_in[9];
    const float* Wpost = (const float*)d_in[10];
    const float* bpost = (const float*)d_in[11];
    const float* Wd    = (const float*)d_in[12];
    const float* bd    = (const float*)d_in[13];
    const float* Wf    = (const float*)d_in[14];
    const float* bf    = (const float*)d_in[15];
    const float* Wc1   = (const float*)d_in[16];
    const float* bc1   = (const float*)d_in[17];
    const float* Wc2   = (const float*)d_in[18];
    const float* bc2   = (const float*)d_in[19];
    float* out = (float*)d_out;

    static bool attr_done = false;
    if (!attr_done) {
        cudaFuncSetAttribute(k_mlp, cudaFuncAttributeMaxDynamicSharedMemorySize, SMEM_BYTES);
        attr_done = true;
    }

    k_prep<<<NCHUNKS, 256>>>(W0, Wpre, Wskip, Wpost, Wf, Wc1);
    k_zero<<<1, 32>>>();
    k_route<<<NPTS / 256, 256>>>(pts, out);
    k_mlp<<<NCTA, NTHR, SMEM_BYTES>>>(pts, vds, aidx, app, b0, bpre, bskip, bpost,
                                      Wd, bd, bf, bc1, Wc2, bc2, out);
}